// round 17
// baseline (speedup 1.0000x reference)
#include <cuda_runtime.h>
#include <cuda_bf16.h>
#include <math.h>

#define NN      8192
#define NFEAT   512
#define NHID    64
#define NHEADS  8
#define NCLASS  40
#define CHUNK   128
#define NCHUNKS (NN / CHUNK)   // 64
#define SEG     2048
#define KP      1536
#define KC      64
#define NCH     (KP / KC)      // 24

typedef unsigned long long u64;

// ----------------------------- scratch (static device globals) ---------------
__device__ __nv_bfloat16 g_Apk[NN * KP];
__device__ __nv_bfloat16 g_Bpk[512 * KP];
__device__ float g_Wa[NFEAT * 16];
__device__ float g_Wa2[NFEAT * 2];
__device__ float g_Wh1[NN * NHEADS * NHID];
__device__ float g_H[NN * NFEAT];
__device__ float g_Wh2[NN * NCLASS];
__device__ float g_f1[NHEADS * NN];
__device__ float g_f1b[NN];
__device__ float g_mean1[NHEADS * NHID];
__device__ float g_mean2[NCLASS];
__device__ float g_P[NHEADS * (NN + 1) * NHID];
__device__ float g_S[NHEADS * (NN + 1)];
__device__ float g_P2[(NN + 1) * NCLASS];
__device__ float g_S2[(NN + 1)];
__device__ u64   g_sortbuf[NHEADS * NN];
__device__ u64   g_sortbuf2[NN];
__device__ float g_AGG1[NHEADS * NCHUNKS * (NHID + 1)];
__device__ float g_INC1[NHEADS * NCHUNKS * (NHID + 1)];
__device__ float g_AGG2[NCHUNKS * (NCLASS + 1)];
__device__ float g_INC2[NCHUNKS * (NCLASS + 1)];
__device__ int   g_flags1[NHEADS * NCHUNKS];
__device__ int   g_flags2[NCHUNKS];
__device__ int   g_bar1;
__device__ int   g_bar2;

// ---------- float <-> order-preserving uint ----------
__device__ __forceinline__ unsigned int ord_of_float(float f) {
    unsigned int u = __float_as_uint(f);
    return u ^ ((u & 0x80000000u) ? 0xFFFFFFFFu : 0x80000000u);
}
__device__ __forceinline__ float float_of_ord(unsigned int o) {
    o = (o & 0x80000000u) ? (o ^ 0x80000000u) : ~o;
    return __uint_as_float(o);
}

__device__ __forceinline__ void ldmx4(unsigned int& r0, unsigned int& r1,
                                      unsigned int& r2, unsigned int& r3,
                                      unsigned int addr) {
    asm volatile("ldmatrix.sync.aligned.m8n8.x4.shared.b16 {%0,%1,%2,%3}, [%4];"
                 : "=r"(r0), "=r"(r1), "=r"(r2), "=r"(r3) : "r"(addr));
}
__device__ __forceinline__ void ldmx2(unsigned int& r0, unsigned int& r1, unsigned int addr) {
    asm volatile("ldmatrix.sync.aligned.m8n8.x2.shared.b16 {%0,%1}, [%2];"
                 : "=r"(r0), "=r"(r1) : "r"(addr));
}
__device__ __forceinline__ void cpasync16(unsigned int dst, const void* src) {
    asm volatile("cp.async.cg.shared.global [%0], [%1], 16;" :: "r"(dst), "l"(src));
}

// ----------------------------- kernels --------------------------------------

__global__ void reset_kernel(int* f1a, int* f2a, float* m1, float* m2,
                             int* bar1, int* bar2) {
    int t = threadIdx.x;
    for (int i = t; i < NHEADS * NCHUNKS; i += 256) f1a[i] = 0;
    for (int i = t; i < NCHUNKS; i += 256) f2a[i] = 0;
    for (int i = t; i < NHEADS * NHID; i += 256) m1[i] = 0.f;
    for (int i = t; i < NCLASS; i += 256) m2[i] = 0.f;
    if (t == 0) { *bar1 = 0; *bar2 = 0; }
}

__global__ void pack_AB_kernel(const float* __restrict__ x, const float* __restrict__ W,
                               __nv_bfloat16* __restrict__ Apk, __nv_bfloat16* __restrict__ Bpk) {
    int idx = blockIdx.x * blockDim.x + threadIdx.x;
    if (idx < NN * NFEAT) {
        int m = idx >> 9, k = idx & 511;
        float v = x[idx];
        __nv_bfloat16 hi = __float2bfloat16(v);
        __nv_bfloat16 lo = __float2bfloat16(v - __bfloat162float(hi));
        size_t base = (size_t)m * KP;
        Apk[base + k] = hi;
        Apk[base + 512 + k] = lo;
        Apk[base + 1024 + k] = hi;
    } else {
        int j = idx - NN * NFEAT;
        if (j >= NFEAT * 512) return;
        int d = j & 63, k = (j >> 6) & 511, h = j >> 15;
        float v = W[((size_t)h * NFEAT + k) * NHID + d];
        __nv_bfloat16 hi = __float2bfloat16(v);
        __nv_bfloat16 lo = __float2bfloat16(v - __bfloat162float(hi));
        int n = h * 64 + d;
        size_t base = (size_t)n * KP;
        Bpk[base + k] = hi;
        Bpk[base + 512 + k] = hi;
        Bpk[base + 1024 + k] = lo;
    }
}

__global__ void compute_Wa_kernel(const float* __restrict__ W, const float* __restrict__ a,
                                  float* __restrict__ Wa) {
    int wid = (blockIdx.x * blockDim.x + threadIdx.x) >> 5;
    int lane = threadIdx.x & 31;
    if (wid >= NHEADS * NFEAT) return;
    int h = wid / NFEAT, k = wid % NFEAT;
    const float* Wrow = W + ((size_t)h * NFEAT + k) * NHID;
    const float* av = a + h * 2 * NHID;
    float s1 = 0.f, s2 = 0.f;
    for (int d = lane; d < NHID; d += 32) {
        float v = Wrow[d];
        s1 += v * av[d];
        s2 += v * av[NHID + d];
    }
#pragma unroll
    for (int o = 16; o; o >>= 1) {
        s1 += __shfl_xor_sync(0xFFFFFFFFu, s1, o);
        s2 += __shfl_xor_sync(0xFFFFFFFFu, s2, o);
    }
    if (lane == 0) {
        Wa[k * 16 + 2 * h]     = s1;
        Wa[k * 16 + 2 * h + 1] = s2;
    }
}

// Wa2[k][0] = Wout[k,:]·a_out[0:40], Wa2[k][1] = Wout[k,:]·a_out[40:80]
__global__ void compute_Wa2_kernel(const float* __restrict__ Wout,
                                   const float* __restrict__ a_out,
                                   float* __restrict__ Wa2) {
    int k = blockIdx.x * blockDim.x + threadIdx.x;
    if (k >= NFEAT) return;
    const float* wr = Wout + (size_t)k * NCLASS;
    float s1 = 0.f, s2 = 0.f;
#pragma unroll
    for (int c = 0; c < NCLASS; c++) {
        float v = wr[c];
        s1 += v * a_out[c];
        s2 += v * a_out[NCLASS + c];
    }
    Wa2[k * 2]     = s1;
    Wa2[k * 2 + 1] = s2;
}

__global__ __launch_bounds__(256) void fx_kernel(
    const float* __restrict__ x, const float* __restrict__ Wa,
    float* __restrict__ f1, u64* __restrict__ buf)
{
    __shared__ float Ws[NFEAT * 17];
    int tid = threadIdx.x;
    for (int idx = tid; idx < NFEAT * 16; idx += 256) {
        int k = idx >> 4, c = idx & 15;
        Ws[k * 17 + c] = Wa[idx];
    }
    __syncthreads();
    int warp = tid >> 5, lane = tid & 31;
    int i = blockIdx.x * 8 + warp;
    const float* xr = x + (size_t)i * NFEAT;
    float acc[16];
#pragma unroll
    for (int c = 0; c < 16; c++) acc[c] = 0.f;
#pragma unroll
    for (int t = 0; t < 16; t++) {
        int k = lane + 32 * t;
        float xv = xr[k];
        const float* w = &Ws[k * 17];
#pragma unroll
        for (int c = 0; c < 16; c++) acc[c] += xv * w[c];
    }
#pragma unroll
    for (int c = 0; c < 16; c++) {
#pragma unroll
        for (int o = 16; o; o >>= 1) acc[c] += __shfl_xor_sync(0xFFFFFFFFu, acc[c], o);
    }
    if (lane == 0) {
#pragma unroll
        for (int h = 0; h < NHEADS; h++) {
            f1[h * NN + i] = acc[2 * h];
            buf[h * NN + i] = ((u64)ord_of_float(acc[2 * h + 1]) << 32) | (unsigned int)i;
        }
    }
}

// -------- split-bf16 GEMM: cp.async + swizzle + ldmatrix + mma.sync ----------
__global__ __launch_bounds__(256, 2) void gemm_mma_kernel(
    const __nv_bfloat16* __restrict__ A,
    const __nv_bfloat16* __restrict__ B,
    float* __restrict__ C)
{
    extern __shared__ char smem[];
    unsigned int sbase;
    {
        size_t sa = __cvta_generic_to_shared(smem);
        sbase = (unsigned int)sa;
    }
    int tid = threadIdx.x;
    int wid = tid >> 5, lane = tid & 31;
    int g = lane >> 2, tig = lane & 3;
    int warpM = wid & 1, warpN = wid >> 1;
    int bm = blockIdx.y * 128, bn = blockIdx.x * 128;

    const __nv_bfloat16* Ag = A + (size_t)bm * KP;
    const __nv_bfloat16* Bg = B + (size_t)bn * KP;

    int arow = (lane & 7) + ((lane >> 3) & 1) * 8;
    int auh = (lane >> 4) & 1;
    int brow = lane & 7;
    int buh = (lane >> 3) & 1;

    float acc[4][4][4];
#pragma unroll
    for (int mt = 0; mt < 4; mt++)
#pragma unroll
        for (int nt = 0; nt < 4; nt++)
#pragma unroll
            for (int q = 0; q < 4; q++) acc[mt][nt][q] = 0.f;

    auto load_chunk = [&](int buf, int c) {
#pragma unroll
        for (int r = 0; r < 4; r++) {
            int idx = tid + r * 256;
            int row = idx >> 3, u = idx & 7;
            unsigned int sw = (unsigned int)((u ^ (row & 7)) << 4) + row * 128;
            cpasync16(sbase + buf * 16384 + sw, Ag + (size_t)row * KP + c * KC + u * 8);
            cpasync16(sbase + 32768 + buf * 16384 + sw, Bg + (size_t)row * KP + c * KC + u * 8);
        }
        asm volatile("cp.async.commit_group;" ::: "memory");
    };

    load_chunk(0, 0);
    load_chunk(1, 1);

    for (int c = 0; c < NCH; c++) {
        if (c + 1 < NCH) asm volatile("cp.async.wait_group 1;" ::: "memory");
        else             asm volatile("cp.async.wait_group 0;" ::: "memory");
        __syncthreads();
        int buf = c & 1;
        unsigned int aBase = sbase + buf * 16384;
        unsigned int bBase = sbase + 32768 + buf * 16384;
#pragma unroll
        for (int ks = 0; ks < 4; ks++) {
            unsigned int bfr[4][2];
#pragma unroll
            for (int nt = 0; nt < 4; nt++) {
                int row = warpN * 32 + nt * 8 + brow;
                int u = ks * 2 + buh;
                ldmx2(bfr[nt][0], bfr[nt][1],
                      bBase + row * 128 + (unsigned int)((u ^ (row & 7)) << 4));
            }
#pragma unroll
            for (int mt = 0; mt < 4; mt++) {
                int row = warpM * 64 + mt * 16 + arow;
                int u = ks * 2 + auh;
                unsigned int a0, a1, a2, a3;
                ldmx4(a0, a1, a2, a3,
                      aBase + row * 128 + (unsigned int)((u ^ (row & 7)) << 4));
#pragma unroll
                for (int nt = 0; nt < 4; nt++) {
                    asm volatile(
                        "mma.sync.aligned.m16n8k16.row.col.f32.bf16.bf16.f32 "
                        "{%0,%1,%2,%3}, {%4,%5,%6,%7}, {%8,%9}, {%0,%1,%2,%3};"
                        : "+f"(acc[mt][nt][0]), "+f"(acc[mt][nt][1]),
                          "+f"(acc[mt][nt][2]), "+f"(acc[mt][nt][3])
                        : "r"(a0), "r"(a1), "r"(a2), "r"(a3),
                          "r"(bfr[nt][0]), "r"(bfr[nt][1]));
                }
            }
        }
        __syncthreads();
        if (c + 2 < NCH) load_chunk(buf, c + 2);
    }

#pragma unroll
    for (int mt = 0; mt < 4; mt++) {
        int row = bm + warpM * 64 + mt * 16 + g;
#pragma unroll
        for (int nt = 0; nt < 4; nt++) {
            int col = bn + warpN * 32 + nt * 8 + tig * 2;
            *(float2*)(C + (size_t)row * 512 + col) =
                make_float2(acc[mt][nt][0], acc[mt][nt][1]);
            *(float2*)(C + (size_t)(row + 8) * 512 + col) =
                make_float2(acc[mt][nt][2], acc[mt][nt][3]);
        }
    }
}

// ---------- fused multi-block bitonic sort (one launch per layer) -----------
#define GBAR()                                                          \
    do {                                                                \
        __syncthreads();                                                \
        __threadfence();                                                \
        gen++;                                                          \
        if (threadIdx.x == 0) {                                         \
            atomicAdd((int*)bar, 1);                                    \
            while (*((volatile int*)bar) < gen * nB) {}                 \
        }                                                               \
        __syncthreads();                                                \
    } while (0)

// compare-exchange for the two elements owned by thread t (2t, 2t+1)
#define CE2(jv, kv)                                                         \
    do {                                                                    \
        int l0 = 2 * t, l1 = 2 * t + 1;                                     \
        int p0 = l0 ^ (jv), p1 = l1 ^ (jv);                                 \
        if (p0 > l0) {                                                      \
            u64 a = s[l0], b = s[p0];                                       \
            bool dir = (((ihead + l0) & (kv)) == 0);                        \
            if (dir ? (a < b) : (a > b)) { s[l0] = b; s[p0] = a; }          \
        }                                                                   \
        if (p1 > l1) {                                                      \
            u64 a = s[l1], b = s[p1];                                       \
            bool dir = (((ihead + l1) & (kv)) == 0);                        \
            if (dir ? (a < b) : (a > b)) { s[l1] = b; s[p1] = a; }          \
        }                                                                   \
    } while (0)

__global__ __launch_bounds__(1024) void fused_sort_kernel(
    u64* __restrict__ buf, int nB, int* bar)
{
    __shared__ u64 s[SEG];
    int base = blockIdx.x * SEG;
    int ihead = base & (NN - 1);
    int t = threadIdx.x;
    int gen = 0;

    // phase A: full local sort (j<=32 steps are warp-local: elems 2t,2t+1)
    for (int l = t; l < SEG; l += 1024) s[l] = buf[base + l];
    __syncthreads();
    for (int k = 2; k <= SEG; k <<= 1) {
        int j = k >> 1;
        for (; j > 32; j >>= 1) { CE2(j, k); __syncthreads(); }
        for (; j > 0; j >>= 1)  { CE2(j, k); __syncwarp(); }
        __syncthreads();
    }
    for (int l = t; l < SEG; l += 1024) __stcg(&buf[base + l], s[l]);
    GBAR();

    // phase B: k=4096, j=2048 cross-segment
    if ((ihead & 2048) == 0) {
        for (int l = t; l < SEG; l += 1024) {
            int i = ihead + l;
            u64 a = __ldcg(&buf[base + l]);
            u64 b = __ldcg(&buf[base + l + 2048]);
            bool dir = ((i & 4096) == 0);
            if (dir ? (a < b) : (a > b)) {
                __stcg(&buf[base + l], b);
                __stcg(&buf[base + l + 2048], a);
            }
        }
    }
    GBAR();

    // phase C: k=4096, local j<=1024
    for (int l = t; l < SEG; l += 1024) s[l] = __ldcg(&buf[base + l]);
    __syncthreads();
    {
        int j = 1024;
        for (; j > 32; j >>= 1) { CE2(j, 4096); __syncthreads(); }
        for (; j > 0; j >>= 1)  { CE2(j, 4096); __syncwarp(); }
        __syncthreads();
    }
    for (int l = t; l < SEG; l += 1024) __stcg(&buf[base + l], s[l]);
    GBAR();

    // phase D: k=8192, j=4096 & 2048 (quad, descending) — segment 0 per head
    if (ihead == 0) {
        u64* bh = buf + base;
        for (int l = t; l < 2048; l += 1024) {
            u64 a0 = __ldcg(&bh[l]),        a1 = __ldcg(&bh[l + 2048]);
            u64 a2 = __ldcg(&bh[l + 4096]), a3 = __ldcg(&bh[l + 6144]);
            u64 tt;
            if (a0 < a2) { tt = a0; a0 = a2; a2 = tt; }
            if (a1 < a3) { tt = a1; a1 = a3; a3 = tt; }
            if (a0 < a1) { tt = a0; a0 = a1; a1 = tt; }
            if (a2 < a3) { tt = a2; a2 = a3; a3 = tt; }
            __stcg(&bh[l], a0); __stcg(&bh[l + 2048], a1);
            __stcg(&bh[l + 4096], a2); __stcg(&bh[l + 6144], a3);
        }
    }
    GBAR();

    // phase E: k=8192, local j<=1024 (descending: (ihead+l)&8192==0 always)
    for (int l = t; l < SEG; l += 1024) s[l] = __ldcg(&buf[base + l]);
    __syncthreads();
    {
        int j = 1024;
        for (; j > 32; j >>= 1) { CE2(j, 8192); __syncthreads(); }
        for (; j > 0; j >>= 1)  { CE2(j, 8192); __syncwarp(); }
        __syncthreads();
    }
    for (int l = t; l < SEG; l += 1024) __stcg(&buf[base + l], s[l]);
}

// ---------- single-pass decoupled-lookback weighted prefix + mean sums ------
__global__ __launch_bounds__(256) void prefix_lookback_kernel(
    const float* __restrict__ Wh, int ld, int colPerHead, int F,
    const u64* __restrict__ buf,
    float* __restrict__ P, float* __restrict__ S,
    volatile float* AGG, volatile float* INC, volatile int* flags,
    float* meanSum)
{
    extern __shared__ float T[];
    __shared__ int   sidx[CHUNK];
    __shared__ float sw[CHUNK];
    __shared__ float aggQ[4][65];
    __shared__ float qexcl[4][65];
    __shared__ float exclSh[65];

    int c = blockIdx.x, h = blockIdx.y;
    int tid = threadIdx.x;
    int q = tid >> 6;
    int d = tid & 63;
    const u64* bh = buf + (size_t)h * NN;
    float kmax = float_of_ord((unsigned int)(bh[0] >> 32));
    if (tid < CHUNK) {
        u64 v = bh[c * CHUNK + tid];
        sidx[tid] = (int)(unsigned int)(v & 0xFFFFFFFFu);
        sw[tid] = expf(float_of_ord((unsigned int)(v >> 32)) - kmax);
    }
    __syncthreads();

    int r0 = q * 32;
    float agg = 0.f, msum = 0.f;
    if (d < F) {
        const float* base = Wh + h * colPerHead + d;
#pragma unroll 4
        for (int r = r0; r < r0 + 32; r++) {
            float xv = base[(size_t)sidx[r] * ld];
            float v = sw[r] * xv;
            T[r * F + d] = v;
            agg += v;
            msum += xv;
        }
        atomicAdd(&meanSum[h * F + d], msum);
        aggQ[q][d] = agg;
    }
    if (d == 0) {
        float s = 0.f;
        for (int r = r0; r < r0 + 32; r++) s += sw[r];
        aggQ[q][64] = s;
    }
    __syncthreads();

    int fidx = h * NCHUNKS + c;
    if (q == 0) {
        if (d < F) {
            float e1 = aggQ[0][d];
            float e2 = e1 + aggQ[1][d];
            float e3 = e2 + aggQ[2][d];
            qexcl[0][d] = 0.f; qexcl[1][d] = e1; qexcl[2][d] = e2; qexcl[3][d] = e3;
            AGG[(size_t)fidx * (F + 1) + d] = e3 + aggQ[3][d];
        }
        if (d == 0) {
            float e1 = aggQ[0][64];
            float e2 = e1 + aggQ[1][64];
            float e3 = e2 + aggQ[2][64];
            qexcl[0][64] = 0.f; qexcl[1][64] = e1; qexcl[2][64] = e2; qexcl[3][64] = e3;
            AGG[(size_t)fidx * (F + 1) + F] = e3 + aggQ[3][64];
        }
    }
    __threadfence();
    __syncthreads();
    if (c > 0 && tid == 0) atomicExch((int*)&flags[fidx], 1);

    if (q == 0) {
        float excl = 0.f, exclS = 0.f;
        if (c > 0) {
            int pd = c - 1;
            while (true) {
                int fidp = h * NCHUNKS + pd;
                int f;
                do { f = flags[fidp]; } while (f == 0);
                volatile float* src = (f == 2) ? (INC + (size_t)fidp * (F + 1))
                                               : (AGG + (size_t)fidp * (F + 1));
                if (d < F) excl += src[d];
                if (d == 0) exclS += src[F];
                if (f == 2) break;
                pd--;
            }
        }
        if (d < F) { exclSh[d] = excl; INC[(size_t)fidx * (F + 1) + d] = excl + qexcl[3][d] + aggQ[3][d]; }
        if (d == 0) { exclSh[64] = exclS; INC[(size_t)fidx * (F + 1) + F] = exclS + qexcl[3][64] + aggQ[3][64]; }
    }
    __threadfence();
    __syncthreads();
    if (tid == 0) atomicExch((int*)&flags[fidx], 2);

    int gbase = c * CHUNK + r0;
    if (d < F) {
        float run = exclSh[d] + qexcl[q][d];
        float* Ph = P + ((size_t)h * (NN + 1)) * F + d;
        for (int r = 0; r < 32; r++) {
            run += T[(r0 + r) * F + d];
            Ph[(size_t)(gbase + r + 1) * F] = run;
        }
    }
    if (d == 0) {
        float runS = exclSh[64] + qexcl[q][64];
        float* Sh = S + (size_t)h * (NN + 1);
        for (int r = 0; r < 32; r++) {
            runS += sw[r0 + r];
            Sh[gbase + r + 1] = runS;
        }
    }
}

// ---------- layer-1 apply + layer-2 f/key computation (H to global) --------
__global__ __launch_bounds__(256) void apply1_f2_kernel(
    const u64* __restrict__ buf1, const float* __restrict__ f1in,
    const float* __restrict__ P, const float* __restrict__ S,
    const float* __restrict__ m1, const float* __restrict__ Wa2,
    float* __restrict__ H, float* __restrict__ f1out, u64* __restrict__ bufout)
{
    __shared__ float Hs[16 * 512];
    __shared__ float wa[512 * 2];
    __shared__ int   sc[128];
    __shared__ float sinv[128];
    int tid = threadIdx.x;
    int row0 = blockIdx.x * 16;

    for (int i = tid; i < 1024; i += 256) wa[i] = Wa2[i];
    if (tid < 128) {
        int r = tid >> 3, h = tid & 7;
        int i = row0 + r;
        const u64* bh = buf1 + (size_t)h * NN;
        float t = f1in[h * NN + i];
        int lo = 0, hi = NN;
        while (lo < hi) {
            int mid = (lo + hi) >> 1;
            float kmid = float_of_ord((unsigned int)(bh[mid] >> 32));
            if (t + kmid > 0.f) lo = mid + 1; else hi = mid;
        }
        sc[tid] = lo;
        sinv[tid] = (lo > 0) ? (1.f / S[(size_t)h * (NN + 1) + lo]) : 0.f;
    }
    __syncthreads();

    for (int idx = tid; idx < 16 * 512; idx += 256) {
        int r = idx >> 9, hd = idx & 511;
        int h = hd >> 6, d = hd & 63;
        int c = sc[r * 8 + h];
        float v;
        if (c > 0) v = P[((size_t)h * (NN + 1) + c) * NHID + d] * sinv[r * 8 + h];
        else       v = m1[h * NHID + d] * (1.f / NN);
        v = (v > 0.f) ? v : (expf(v) - 1.f);
        Hs[idx] = v;
        H[(size_t)row0 * 512 + idx] = v;
    }
    __syncthreads();

    int warp = tid >> 5, lane = tid & 31;
    int r0 = warp * 2;
    float s1a = 0.f, s2a = 0.f, s1b = 0.f, s2b = 0.f;
#pragma unroll
    for (int t = 0; t < 16; t++) {
        int kk = lane + 32 * t;
        float w1 = wa[kk * 2], w2 = wa[kk * 2 + 1];
        float xA = Hs[r0 * 512 + kk];
        float xB = Hs[(r0 + 1) * 512 + kk];
        s1a += xA * w1; s2a += xA * w2;
        s1b += xB * w1; s2b += xB * w2;
    }
#pragma unroll
    for (int o = 16; o; o >>= 1) {
        s1a += __shfl_xor_sync(0xFFFFFFFFu, s1a, o);
        s2a += __shfl_xor_sync(0xFFFFFFFFu, s2a, o);
        s1b += __shfl_xor_sync(0xFFFFFFFFu, s1b, o);
        s2b += __shfl_xor_sync(0xFFFFFFFFu, s2b, o);
    }
    if (lane == 0) {
        int gr0 = row0 + r0;
        f1out[gr0] = s1a;
        f1out[gr0 + 1] = s1b;
        bufout[gr0] = ((u64)ord_of_float(s2a) << 32) | (unsigned int)gr0;
        bufout[gr0 + 1] = ((u64)ord_of_float(s2b) << 32) | (unsigned int)(gr0 + 1);
    }
}

// ---------- layer-2 GEMM: Wh2 = H @ Wout (64 rows/block) --------------------
__global__ __launch_bounds__(256) void gemm2_kernel(
    const float* __restrict__ H, const float* __restrict__ Wout,
    float* __restrict__ Wh2)
{
    extern __shared__ float Ws[];   // 512 * 41
    int tid = threadIdx.x;
    for (int idx = tid; idx < NFEAT * NCLASS; idx += 256) {
        int k = idx / NCLASS, cc = idx % NCLASS;
        Ws[k * 41 + cc] = Wout[idx];
    }
    __syncthreads();

    int warp = tid >> 5, lane = tid & 31;
#pragma unroll
    for (int grp = 0; grp < 4; grp++) {
        int gr0 = blockIdx.x * 64 + grp * 16 + warp * 2;
        const float* h0 = H + (size_t)gr0 * NFEAT;
        const float* h1 = h0 + NFEAT;
        float xA[16], xB[16];
#pragma unroll
        for (int t = 0; t < 16; t++) {
            xA[t] = h0[lane + 32 * t];
            xB[t] = h1[lane + 32 * t];
        }
        float acc0[NCLASS], acc1[NCLASS];
#pragma unroll
        for (int cc = 0; cc < NCLASS; cc++) { acc0[cc] = 0.f; acc1[cc] = 0.f; }
#pragma unroll
        for (int t = 0; t < 16; t++) {
            const float* wr = &Ws[(lane + 32 * t) * 41];
#pragma unroll
            for (int cc = 0; cc < NCLASS; cc++) {
                float wv = wr[cc];
                acc0[cc] += xA[t] * wv;
                acc1[cc] += xB[t] * wv;
            }
        }
#pragma unroll
        for (int cc = 0; cc < NCLASS; cc++) {
#pragma unroll
            for (int o = 16; o; o >>= 1) {
                acc0[cc] += __shfl_xor_sync(0xFFFFFFFFu, acc0[cc], o);
                acc1[cc] += __shfl_xor_sync(0xFFFFFFFFu, acc1[cc], o);
            }
        }
        if (lane < 32) {
            Wh2[(size_t)gr0 * NCLASS + lane] = acc0[lane];
            Wh2[(size_t)(gr0 + 1) * NCLASS + lane] = acc1[lane];
        }
        if (lane < 8) {
            Wh2[(size_t)gr0 * NCLASS + 32 + lane] = acc0[32 + lane];
            Wh2[(size_t)(gr0 + 1) * NCLASS + 32 + lane] = acc1[32 + lane];
        }
    }
}

__global__ void apply2_lsm_kernel(
    const u64* __restrict__ buf, const float* __restrict__ f1,
    const float* __restrict__ P2, const float* __restrict__ S2,
    const float* __restrict__ meanSum2, float* __restrict__ out)
{
    int i = blockIdx.x * (blockDim.x >> 5) + (threadIdx.x >> 5);
    int lane = threadIdx.x & 31;
    if (i >= NN) return;
    float t = f1[i];
    int lo = 0, hi = NN;
    while (lo < hi) {
        int mid = (lo + hi) >> 1;
        float kmid = float_of_ord((unsigned int)(buf[mid] >> 32));
        if (t + kmid > 0.f) lo = mid + 1; else hi = mid;
    }
    int c = lo;
    float inv = (c > 0) ? (1.f / S2[c]) : 0.f;
    float v0, v1;
    if (c > 0) {
        v0 = P2[(size_t)c * NCLASS + lane] * inv;
        v1 = (lane < 8) ? P2[(size_t)c * NCLASS + 32 + lane] * inv : 0.f;
    } else {
        v0 = meanSum2[lane] * (1.f / NN);
        v1 = (lane < 8) ? meanSum2[32 + lane] * (1.f / NN) : 0.f;
    }
    v0 = (v0 > 0.f) ? v0 : (expf(v0) - 1.f);
    v1 = (v1 > 0.f) ? v1 : (expf(v1) - 1.f);
    float m0 = v0;
    float m1 = (lane < 8) ? v1 : -INFINITY;
    float mx = fmaxf(m0, m1);
#pragma unroll
    for (int o = 16; o; o >>= 1) mx = fmaxf(mx, __shfl_xor_sync(0xFFFFFFFFu, mx, o));
    float se = expf(v0 - mx) + ((lane < 8) ? expf(v1 - mx) : 0.f);
#pragma unroll
    for (int o = 16; o; o >>= 1) se += __shfl_xor_sync(0xFFFFFFFFu, se, o);
    float lse = mx + logf(se);
    out[(size_t)i * NCLASS + lane] = v0 - lse;
    if (lane < 8) out[(size_t)i * NCLASS + 32 + lane] = v1 - lse;
}

// ----------------------------- host launcher --------------------------------
extern "C" void kernel_launch(void* const* d_in, const int* in_sizes, int n_in,
                              void* d_out, int out_size)
{
    const float* x       = (const float*)d_in[0];
    const float* W_heads = (const float*)d_in[2];
    const float* a_heads = (const float*)d_in[3];
    const float* W_out   = (const float*)d_in[4];
    const float* a_out   = (const float*)d_in[5];
    float* out = (float*)d_out;

    float *Wa, *Wa2g, *Wh1, *Hg, *Wh2, *f1, *f1b, *m1, *m2, *P, *S, *P2, *S2;
    float *AGG1, *INC1, *AGG2, *INC2;
    int *fl1, *fl2, *bar1, *bar2;
    u64 *sbuf, *sbuf2;
    __nv_bfloat16 *Apk, *Bpk;
    cudaGetSymbolAddress((void**)&Apk,   g_Apk);
    cudaGetSymbolAddress((void**)&Bpk,   g_Bpk);
    cudaGetSymbolAddress((void**)&Wa,    g_Wa);
    cudaGetSymbolAddress((void**)&Wa2g,  g_Wa2);
    cudaGetSymbolAddress((void**)&Wh1,   g_Wh1);
    cudaGetSymbolAddress((void**)&Hg,    g_H);
    cudaGetSymbolAddress((void**)&Wh2,   g_Wh2);
    cudaGetSymbolAddress((void**)&f1,    g_f1);
    cudaGetSymbolAddress((void**)&f1b,   g_f1b);
    cudaGetSymbolAddress((void**)&m1,    g_mean1);
    cudaGetSymbolAddress((void**)&m2,    g_mean2);
    cudaGetSymbolAddress((void**)&P,     g_P);
    cudaGetSymbolAddress((void**)&S,     g_S);
    cudaGetSymbolAddress((void**)&P2,    g_P2);
    cudaGetSymbolAddress((void**)&S2,    g_S2);
    cudaGetSymbolAddress((void**)&AGG1,  g_AGG1);
    cudaGetSymbolAddress((void**)&INC1,  g_INC1);
    cudaGetSymbolAddress((void**)&AGG2,  g_AGG2);
    cudaGetSymbolAddress((void**)&INC2,  g_INC2);
    cudaGetSymbolAddress((void**)&fl1,   g_flags1);
    cudaGetSymbolAddress((void**)&fl2,   g_flags2);
    cudaGetSymbolAddress((void**)&bar1,  g_bar1);
    cudaGetSymbolAddress((void**)&bar2,  g_bar2);
    cudaGetSymbolAddress((void**)&sbuf,  g_sortbuf);
    cudaGetSymbolAddress((void**)&sbuf2, g_sortbuf2);

    static cudaStream_t s2 = nullptr;
    static cudaEvent_t evFork = nullptr, evSort = nullptr, evApply = nullptr, evSort2 = nullptr;
    static bool attrDone = false;
    if (!s2) {
        cudaStreamCreateWithFlags(&s2, cudaStreamNonBlocking);
        cudaEventCreateWithFlags(&evFork, cudaEventDisableTiming);
        cudaEventCreateWithFlags(&evSort, cudaEventDisableTiming);
        cudaEventCreateWithFlags(&evApply, cudaEventDisableTiming);
        cudaEventCreateWithFlags(&evSort2, cudaEventDisableTiming);
    }
    if (!attrDone) {
        cudaFuncSetAttribute(gemm2_kernel,
                             cudaFuncAttributeMaxDynamicSharedMemorySize, NFEAT * 41 * 4);
        cudaFuncSetAttribute(fx_kernel,
                             cudaFuncAttributeMaxDynamicSharedMemorySize, NFEAT * 17 * 4);
        cudaFuncSetAttribute(gemm_mma_kernel,
                             cudaFuncAttributeMaxDynamicSharedMemorySize, 65536);
        attrDone = true;
    }

    // fork side stream from the capture stream at t=0
    cudaEventRecord(evFork, 0);
    cudaStreamWaitEvent(s2, evFork, 0);

    // side stream: reset + Wa/Wa2 + fx + fused layer-1 sort
    reset_kernel<<<1, 256, 0, s2>>>(fl1, fl2, m1, m2, bar1, bar2);
    compute_Wa_kernel<<<(NHEADS * NFEAT * 32 + 255) / 256, 256, 0, s2>>>(W_heads, a_heads, Wa);
    compute_Wa2_kernel<<<2, 256, 0, s2>>>(W_out, a_out, Wa2g);
    fx_kernel<<<NN / 8, 256, 0, s2>>>(x, Wa, f1, sbuf);
    fused_sort_kernel<<<NHEADS * NN / SEG, 1024, 0, s2>>>(sbuf, NHEADS * NN / SEG, bar1);
    cudaEventRecord(evSort, s2);

    // main stream: pack + HMMA GEMM (concurrent with side stream)
    pack_AB_kernel<<<(NN * NFEAT + NFEAT * 512 + 255) / 256, 256>>>(x, W_heads, Apk, Bpk);
    {
        dim3 grid(512 / 128, NN / 128);
        gemm_mma_kernel<<<grid, 256, 65536>>>(Apk, Bpk, Wh1);
    }

    cudaStreamWaitEvent(0, evSort, 0);
    {
        dim3 grid(NCHUNKS, NHEADS);
        prefix_lookback_kernel<<<grid, 256, CHUNK * NHID * 4>>>(
            Wh1, NHEADS * NHID, NHID, NHID, sbuf, P, S, AGG1, INC1, fl1, m1);
    }

    // apply layer-1 attention, emit H + layer-2 f/keys
    apply1_f2_kernel<<<NN / 16, 256>>>(sbuf, f1, P, S, m1, Wa2g, Hg, f1b, sbuf2);
    cudaEventRecord(evApply, 0);

    // side stream: layer-2 sort overlapped with layer-2 GEMM on main
    cudaStreamWaitEvent(s2, evApply, 0);
    fused_sort_kernel<<<NN / SEG, 1024, 0, s2>>>(sbuf2, NN / SEG, bar2);
    cudaEventRecord(evSort2, s2);

    gemm2_kernel<<<NN / 64, 256, NFEAT * 41 * 4>>>(Hg, W_out, Wh2);

    cudaStreamWaitEvent(0, evSort2, 0);
    {
        dim3 grid(NCHUNKS, 1);
        prefix_lookback_kernel<<<grid, 256, CHUNK * NCLASS * 4>>>(
            Wh2, NCLASS, 0, NCLASS, sbuf2, P2, S2, AGG2, INC2, fl2, m2);
    }
    apply2_lsm_kernel<<<(NN + 7) / 8, 256>>>(sbuf2, f1b, P2, S2, m2, out);
}